// round 13
// baseline (speedup 1.0000x reference)
#include <cuda_runtime.h>
#include <cuda_fp16.h>

// Problem constants (fixed by the dataset)
#define NN    50000
#define E0C   800000
#define HEADS 16
#define HD    8
#define HIDD  128

// ---------------- scratch (device globals, no allocation) ----------------
__device__ __align__(16) __half   g_xh16[NN * HIDD];  // fp16 x@W (message path)
__device__ __align__(16) float    g_h[NN * HIDD];     // layer-1 output
__device__ __align__(16) float    g_als[NN * HEADS];
__device__ __align__(16) float    g_ald[NN * HEADS];
__device__ __align__(16) unsigned g_wtf1[HIDD * HIDD]; // W1 pre-converted to tf32
__device__ __align__(16) unsigned g_wtf2[HIDD * HIDD]; // W2 pre-converted to tf32

// CSR (by dst), built once per call.
// INVARIANT: g_deg all-zero on entry (zero-init at load; csr_scan re-zeroes).
__device__ int g_deg[NN];
__device__ int g_off[NN + 1];
__device__ int g_cur[NN];
__device__ int g_srclist[E0C];

__device__ __forceinline__ unsigned f2tf32(float f) {
    unsigned r;
    asm("cvt.rna.tf32.f32 %0, %1;" : "=r"(r) : "f"(f));
    return r;
}

// ---------------- one-time W conversion (RNA) -------------------------------
__global__ void wconv_kernel(const float* __restrict__ W1,
                             const float* __restrict__ W2) {
    int i = blockIdx.x * blockDim.x + threadIdx.x;
    if (i < HIDD * HIDD) {
        g_wtf1[i] = f2tf32(__ldg(W1 + i));
        g_wtf2[i] = f2tf32(__ldg(W2 + i));
    }
}

// ---------------- CSR build -------------------------------------------------
__global__ void csr_hist_kernel(const int* __restrict__ ei) {
    int e = blockIdx.x * blockDim.x + threadIdx.x;
    if (e >= E0C) return;
    atomicAdd(&g_deg[__ldg(ei + E0C + e)], 1);
}

__global__ void csr_scan_kernel() {
    __shared__ int partial[1024];
    const int t = threadIdx.x;
    const int CH = (NN + 1023) / 1024;   // 49
    const int start = t * CH;

    int sum = 0;
    for (int i = 0; i < CH; i++) {
        int n = start + i;
        if (n < NN) sum += g_deg[n];
    }
    partial[t] = sum;
    __syncthreads();
    for (int off = 1; off < 1024; off <<= 1) {
        int v = (t >= off) ? partial[t - off] : 0;
        __syncthreads();
        partial[t] += v;
        __syncthreads();
    }
    int run = (t == 0) ? 0 : partial[t - 1];
    for (int i = 0; i < CH; i++) {
        int n = start + i;
        if (n < NN) {
            int d = g_deg[n];
            g_off[n] = run;
            g_cur[n] = run;
            run += d;
            g_deg[n] = 0;   // restore invariant for next call
        }
    }
    if (t == 1023) g_off[NN] = run;
}

__global__ void csr_scatter_kernel(const int* __restrict__ ei) {
    int e = blockIdx.x * blockDim.x + threadIdx.x;
    if (e >= E0C) return;
    int src = __ldg(ei + e);
    int dst = __ldg(ei + E0C + e);
    int pos = atomicAdd(&g_cur[dst], 1);
    g_srclist[pos] = src;
}

// ---------------- tf32 tensor-core GEMM v4 (cvt-free staging) ---------------
// 64 rows/block (grid 782), 8 warps: wr=w&3 -> rows [16wr,16wr+16),
// jh=(w>>2)*8 -> j-tiles [jh,jh+8). W copied from pre-converted tf32 global;
// A staged as RAW fp32 bits (HW truncates to tf32). 106.5 KB smem, 2 CTAs/SM,
// one barrier, then pure LDS+MMA.
#define WS_PITCH 136   // words; 136 % 32 == 8 -> conflict-free frag loads
#define A_PITCH  72    // words; 72 % 32 == 8  -> same property
#define GEMM_ROWS 64
#define GEMM_SMEM_BYTES ((128 * WS_PITCH + 128 * A_PITCH) * 4)   // 106,496 B

__device__ __forceinline__ void mma_tf32(float& d0, float& d1, float& d2, float& d3,
                                         unsigned a0, unsigned a1, unsigned a2, unsigned a3,
                                         unsigned b0, unsigned b1) {
    asm volatile(
        "mma.sync.aligned.m16n8k8.row.col.f32.tf32.tf32.f32 "
        "{%0,%1,%2,%3},{%4,%5,%6,%7},{%8,%9},{%0,%1,%2,%3};"
        : "+f"(d0), "+f"(d1), "+f"(d2), "+f"(d3)
        : "r"(a0), "r"(a1), "r"(a2), "r"(a3), "r"(b0), "r"(b1));
}

template <int LAYER>
__global__ void __launch_bounds__(256, 2) gemm_kernel(
        const float* __restrict__ X,
        const float* __restrict__ a_src,
        const float* __restrict__ a_dst, int M) {
    const float*    A  = (LAYER == 0) ? X : g_h;
    const unsigned* Wt = (LAYER == 0) ? g_wtf1 : g_wtf2;

    extern __shared__ unsigned smem_u[];
    unsigned* Ws  = smem_u;                     // [128 k][WS_PITCH] tf32 W
    unsigned* Ast = smem_u + 128 * WS_PITCH;    // [128 col][A_PITCH] raw-fp32 A^T

    const int tid  = threadIdx.x;   // 256
    const int lane = tid & 31;
    const int w    = tid >> 5;
    const int wr   = w & 3;         // rows [16wr, 16wr+16)
    const int jh   = (w >> 2) * 8;  // j-tiles [jh, jh+8)
    const int g    = lane >> 2;
    const int t    = lane & 3;
    const int row0 = blockIdx.x * GEMM_ROWS;

    // ---- stage W: plain uint4 copies (already tf32) ----
#pragma unroll
    for (int it = 0; it < 16; it++) {
        int v = tid + it * 256;
        int k = v >> 5;
        int n4 = (v & 31) << 2;
        uint4 wv = *reinterpret_cast<const uint4*>(Wt + (size_t)k * HIDD + n4);
        *reinterpret_cast<uint4*>(Ws + k * WS_PITCH + n4) = wv;
    }

    // ---- stage A^T tile: raw fp32 bits (HW truncation to tf32) ----
    {
        int r = tid >> 2;            // row 0..63
        int q = tid & 3;             // col quarter
        int grow = row0 + r;
        bool ok = grow < M;
#pragma unroll
        for (int it = 0; it < 8; it++) {
            int c4 = (q * 8 + it) << 2;   // 0..124
            uint4 av = make_uint4(0u, 0u, 0u, 0u);
            if (ok)
                av = *reinterpret_cast<const uint4*>(A + (size_t)grow * HIDD + c4);
            Ast[(c4 + 0) * A_PITCH + r] = av.x;
            Ast[(c4 + 1) * A_PITCH + r] = av.y;
            Ast[(c4 + 2) * A_PITCH + r] = av.z;
            Ast[(c4 + 3) * A_PITCH + r] = av.w;
        }
    }
    __syncthreads();   // the ONLY barrier

    float acc[8][4];
#pragma unroll
    for (int j = 0; j < 8; j++)
#pragma unroll
        for (int c = 0; c < 4; c++) acc[j][c] = 0.f;

    // ---- 16 k-steps, no barriers ----
#pragma unroll 4
    for (int ks = 0; ks < 16; ks++) {
        const int k0 = ks * 8;
        unsigned a0 = Ast[(k0 + t) * A_PITCH + 16 * wr + g];
        unsigned a1 = Ast[(k0 + t) * A_PITCH + 16 * wr + g + 8];
        unsigned a2 = Ast[(k0 + t + 4) * A_PITCH + 16 * wr + g];
        unsigned a3 = Ast[(k0 + t + 4) * A_PITCH + 16 * wr + g + 8];
        const unsigned* wb0 = Ws + (k0 + t) * WS_PITCH + g + 8 * jh;
        const unsigned* wb1 = Ws + (k0 + t + 4) * WS_PITCH + g + 8 * jh;
#pragma unroll
        for (int j = 0; j < 8; j++) {
            unsigned b0 = wb0[8 * j];
            unsigned b1 = wb1[8 * j];
            mma_tf32(acc[j][0], acc[j][1], acc[j][2], acc[j][3],
                     a0, a1, a2, a3, b0, b1);
        }
    }

    // ---- epilogue: fp16 store + per-head logits (head = global j) ----
    const int rw = row0 + 16 * wr;
#pragma unroll
    for (int j = 0; j < 8; j++) {
        const int jg = jh + j;
        float c0 = acc[j][0], c1 = acc[j][1], c2 = acc[j][2], c3 = acc[j][3];
        int colb = 8 * jg + 2 * t;
        float2 sv = __ldg(reinterpret_cast<const float2*>(a_src + colb));
        float2 dv = __ldg(reinterpret_cast<const float2*>(a_dst + colb));
        float s0 = c0 * sv.x + c1 * sv.y;
        float d0 = c0 * dv.x + c1 * dv.y;
        float s1 = c2 * sv.x + c3 * sv.y;
        float d1 = c2 * dv.x + c3 * dv.y;
        s0 += __shfl_xor_sync(0xffffffffu, s0, 1);
        s0 += __shfl_xor_sync(0xffffffffu, s0, 2);
        d0 += __shfl_xor_sync(0xffffffffu, d0, 1);
        d0 += __shfl_xor_sync(0xffffffffu, d0, 2);
        s1 += __shfl_xor_sync(0xffffffffu, s1, 1);
        s1 += __shfl_xor_sync(0xffffffffu, s1, 2);
        d1 += __shfl_xor_sync(0xffffffffu, d1, 1);
        d1 += __shfl_xor_sync(0xffffffffu, d1, 2);

        int r0v = rw + g, r1v = rw + g + 8;
        if (r0v < M) {
            __half2 p = __floats2half2_rn(c0, c1);
            *reinterpret_cast<__half2*>(g_xh16 + (size_t)r0v * HIDD + colb) = p;
            if (t == 0) {
                g_als[r0v * HEADS + jg] = s0;
                g_ald[r0v * HEADS + jg] = d0;
            }
        }
        if (r1v < M) {
            __half2 p = __floats2half2_rn(c2, c3);
            *reinterpret_cast<__half2*>(g_xh16 + (size_t)r1v * HIDD + colb) = p;
            if (t == 0) {
                g_als[r1v * HEADS + jg] = s1;
                g_ald[r1v * HEADS + jg] = d1;
            }
        }
    }
}

// ---------------- fused aggregation (R8 version — best measured) -----------
__device__ __forceinline__ void load_msg8(const __half* p, float* f) {
    uint4 raw = __ldg(reinterpret_cast<const uint4*>(p));
    const __half2* h = reinterpret_cast<const __half2*>(&raw);
#pragma unroll
    for (int i = 0; i < 4; i++) {
        float2 v = __half22float2(h[i]);
        f[2 * i]     = v.x;
        f[2 * i + 1] = v.y;
    }
}

template <int LAYER>
__global__ void aggregate_kernel(const float* __restrict__ bias,
                                 float* __restrict__ outbuf) {
    const int warp = (blockIdx.x * blockDim.x + threadIdx.x) >> 5;
    if (warp >= NN) return;
    const int lane = threadIdx.x & 31;
    const int hl   = lane & 15;
    const int odd  = lane >> 4;
    const int n = warp;

    const float ald_h = __ldg(g_ald + n * HEADS + hl);

    float acc[8];
    float denom;

    {
        float v = __ldg(g_als + n * HEADS + hl) + ald_h;
        float lr = v > 0.f ? v : 0.2f * v;
        float ex = odd ? 0.f : __expf(lr);
        float f[8];
        load_msg8(g_xh16 + (size_t)n * HIDD + hl * 8, f);
#pragma unroll
        for (int i = 0; i < 8; i++) acc[i] = ex * f[i];
        denom = ex;
    }

    const int beg = __ldg(g_off + n);
    const int end = __ldg(g_off + n + 1);
    const int deg = end - beg;

    for (int j0 = 0; j0 < deg; j0 += 32) {
        int myidx = beg + j0 + lane;
        int s = (myidx < end) ? __ldg(g_srclist + myidx) : 0;
        int cnt = min(32, deg - j0);
#pragma unroll 4
        for (int k = 0; k < cnt; k += 2) {
            int pick = k + odd;
            int src = __shfl_sync(0xffffffffu, s, pick & 31);
            bool valid = pick < cnt;
            float v = __ldg(g_als + src * HEADS + hl) + ald_h;
            float lr = v > 0.f ? v : 0.2f * v;
            float ex = valid ? __expf(lr) : 0.f;
            float f[8];
            load_msg8(g_xh16 + (size_t)src * HIDD + hl * 8, f);
#pragma unroll
            for (int i = 0; i < 8; i++) acc[i] = fmaf(ex, f[i], acc[i]);
            denom += ex;
        }
    }

#pragma unroll
    for (int i = 0; i < 8; i++)
        acc[i] += __shfl_down_sync(0xffffffffu, acc[i], 16);
    denom += __shfl_down_sync(0xffffffffu, denom, 16);

    if (!odd) {
        float inv = 1.f / (denom + 1e-16f);
        float4 b0 = *reinterpret_cast<const float4*>(bias + hl * 8);
        float4 b1 = *reinterpret_cast<const float4*>(bias + hl * 8 + 4);
        float4 r0, r1;
        r0.x = acc[0] * inv + b0.x;
        r0.y = acc[1] * inv + b0.y;
        r0.z = acc[2] * inv + b0.z;
        r0.w = acc[3] * inv + b0.w;
        r1.x = acc[4] * inv + b1.x;
        r1.y = acc[5] * inv + b1.y;
        r1.z = acc[6] * inv + b1.z;
        r1.w = acc[7] * inv + b1.w;
        if (LAYER == 0) {
            r0.x = r0.x > 0.f ? r0.x : expm1f(r0.x);
            r0.y = r0.y > 0.f ? r0.y : expm1f(r0.y);
            r0.z = r0.z > 0.f ? r0.z : expm1f(r0.z);
            r0.w = r0.w > 0.f ? r0.w : expm1f(r0.w);
            r1.x = r1.x > 0.f ? r1.x : expm1f(r1.x);
            r1.y = r1.y > 0.f ? r1.y : expm1f(r1.y);
            r1.z = r1.z > 0.f ? r1.z : expm1f(r1.z);
            r1.w = r1.w > 0.f ? r1.w : expm1f(r1.w);
            *reinterpret_cast<float4*>(g_h + (size_t)n * HIDD + hl * 8)     = r0;
            *reinterpret_cast<float4*>(g_h + (size_t)n * HIDD + hl * 8 + 4) = r1;
        } else {
            *reinterpret_cast<float4*>(outbuf + (size_t)n * HIDD + hl * 8)     = r0;
            *reinterpret_cast<float4*>(outbuf + (size_t)n * HIDD + hl * 8 + 4) = r1;
        }
    }
}

// ---------------- launch ------------------------------------------------------
extern "C" void kernel_launch(void* const* d_in, const int* in_sizes, int n_in,
                              void* d_out, int out_size) {
    const float* x   = (const float*)d_in[0];
    const int*   ei  = (const int*)d_in[1];
    const float* W1  = (const float*)d_in[2];
    const float* as1 = (const float*)d_in[3];
    const float* ad1 = (const float*)d_in[4];
    const float* b1  = (const float*)d_in[5];
    const float* W2  = (const float*)d_in[6];
    const float* as2 = (const float*)d_in[7];
    const float* ad2 = (const float*)d_in[8];
    const float* b2  = (const float*)d_in[9];
    float* out = (float*)d_out;

    cudaFuncSetAttribute(gemm_kernel<0>, cudaFuncAttributeMaxDynamicSharedMemorySize,
                         GEMM_SMEM_BYTES);
    cudaFuncSetAttribute(gemm_kernel<1>, cudaFuncAttributeMaxDynamicSharedMemorySize,
                         GEMM_SMEM_BYTES);

    const int TB = 256;
    const int gGemm = (NN + GEMM_ROWS - 1) / GEMM_ROWS;   // 782
    const int gEdge = (E0C + TB - 1) / TB;
    const int gAgg  = (NN * 32 + TB - 1) / TB;   // one warp per node
    const int gW    = (HIDD * HIDD + TB - 1) / TB;

    // ---- one-time W tf32 conversion + CSR build ----
    wconv_kernel<<<gW, TB>>>(W1, W2);
    csr_hist_kernel<<<gEdge, TB>>>(ei);
    csr_scan_kernel<<<1, 1024>>>();
    csr_scatter_kernel<<<gEdge, TB>>>(ei);

    // ---- layer 1 ----
    gemm_kernel<0><<<gGemm, TB, GEMM_SMEM_BYTES>>>(x, as1, ad1, NN);
    aggregate_kernel<0><<<gAgg, TB>>>(b1, nullptr);

    // ---- layer 2 ----
    gemm_kernel<1><<<gGemm, TB, GEMM_SMEM_BYTES>>>(nullptr, as2, ad2, NN);
    aggregate_kernel<1><<<gAgg, TB>>>(b2, out);
}

// round 14
// speedup vs baseline: 1.0140x; 1.0140x over previous
#include <cuda_runtime.h>
#include <cuda_fp16.h>

// Problem constants (fixed by the dataset)
#define NN    50000
#define E0C   800000
#define HEADS 16
#define HD    8
#define HIDD  128

// ---------------- scratch (device globals, no allocation) ----------------
__device__ __align__(16) __half   g_xh16[NN * HIDD];  // fp16 x@W (message path)
__device__ __align__(16) float    g_h[NN * HIDD];     // layer-1 output
__device__ __align__(16) float    g_als[NN * HEADS];
__device__ __align__(16) float    g_ald[NN * HEADS];

#define WS_PITCH 136   // words; 136 % 32 == 8 -> conflict-free frag loads
// W pre-converted to tf32 AND pre-swizzled to pitch-136 rows, so one linear
// cp.async.bulk drops it into smem in the exact mainloop layout.
__device__ __align__(16) unsigned g_wtf1[HIDD * WS_PITCH];
__device__ __align__(16) unsigned g_wtf2[HIDD * WS_PITCH];

// CSR (by dst), built once per call.
// INVARIANT: g_deg all-zero on entry (zero-init at load; csr_scan re-zeroes).
__device__ int g_deg[NN];
__device__ int g_off[NN + 1];
__device__ int g_cur[NN];
__device__ int g_srclist[E0C];

__device__ __forceinline__ unsigned f2tf32(float f) {
    unsigned r;
    asm("cvt.rna.tf32.f32 %0, %1;" : "=r"(r) : "f"(f));
    return r;
}

// ---------------- one-time W convert + swizzle ------------------------------
__global__ void wconv_kernel(const float* __restrict__ W1,
                             const float* __restrict__ W2) {
    int i = blockIdx.x * blockDim.x + threadIdx.x;
    if (i < HIDD * HIDD) {
        int k = i >> 7, n = i & 127;
        g_wtf1[k * WS_PITCH + n] = f2tf32(__ldg(W1 + i));
        g_wtf2[k * WS_PITCH + n] = f2tf32(__ldg(W2 + i));
    }
}

// ---------------- CSR build -------------------------------------------------
__global__ void csr_hist_kernel(const int* __restrict__ ei) {
    int e = blockIdx.x * blockDim.x + threadIdx.x;
    if (e >= E0C) return;
    atomicAdd(&g_deg[__ldg(ei + E0C + e)], 1);
}

__global__ void csr_scan_kernel() {
    __shared__ int partial[1024];
    const int t = threadIdx.x;
    const int CH = (NN + 1023) / 1024;   // 49
    const int start = t * CH;

    int sum = 0;
    for (int i = 0; i < CH; i++) {
        int n = start + i;
        if (n < NN) sum += g_deg[n];
    }
    partial[t] = sum;
    __syncthreads();
    for (int off = 1; off < 1024; off <<= 1) {
        int v = (t >= off) ? partial[t - off] : 0;
        __syncthreads();
        partial[t] += v;
        __syncthreads();
    }
    int run = (t == 0) ? 0 : partial[t - 1];
    for (int i = 0; i < CH; i++) {
        int n = start + i;
        if (n < NN) {
            int d = g_deg[n];
            g_off[n] = run;
            g_cur[n] = run;
            run += d;
            g_deg[n] = 0;   // restore invariant for next call
        }
    }
    if (t == 1023) g_off[NN] = run;
}

__global__ void csr_scatter_kernel(const int* __restrict__ ei) {
    int e = blockIdx.x * blockDim.x + threadIdx.x;
    if (e >= E0C) return;
    int src = __ldg(ei + e);
    int dst = __ldg(ei + E0C + e);
    int pos = atomicAdd(&g_cur[dst], 1);
    g_srclist[pos] = src;
}

// ---------------- tf32 tensor-core GEMM (R8 structure + bulk-copy W) --------
// 128 rows/block, 8 warps (16 rows each), 16 j-tiles per warp.
// W: ONE cp.async.bulk of the pre-swizzled tf32 image (no LDG/STS/cvt),
// completion via mbarrier, waited once before the first B-frag use.
// A: staged per k-step with RNA cvt (precision-critical).
#define GEMM_ROWS 128
#define GEMM_SMEM_WORDS (128 * WS_PITCH + 8 * WS_PITCH)
#define GEMM_SMEM_BYTES (GEMM_SMEM_WORDS * 4 + 16)   // + mbarrier slot
#define W_BYTES (HIDD * WS_PITCH * 4)                 // 69,632

__device__ __forceinline__ void mma_tf32(float& d0, float& d1, float& d2, float& d3,
                                         unsigned a0, unsigned a1, unsigned a2, unsigned a3,
                                         unsigned b0, unsigned b1) {
    asm volatile(
        "mma.sync.aligned.m16n8k8.row.col.f32.tf32.tf32.f32 "
        "{%0,%1,%2,%3},{%4,%5,%6,%7},{%8,%9},{%0,%1,%2,%3};"
        : "+f"(d0), "+f"(d1), "+f"(d2), "+f"(d3)
        : "r"(a0), "r"(a1), "r"(a2), "r"(a3), "r"(b0), "r"(b1));
}

__device__ __forceinline__ void mbar_wait0(unsigned mbar) {
    asm volatile(
        "{\n\t.reg .pred P;\n"
        "WAIT%=:\n\t"
        "mbarrier.try_wait.parity.shared::cta.b64 P, [%0], 0;\n\t"
        "@!P bra WAIT%=;\n\t}"
        :: "r"(mbar) : "memory");
}

template <int LAYER>
__global__ void gemm_kernel(const float* __restrict__ X,
                            const float* __restrict__ a_src,
                            const float* __restrict__ a_dst, int M) {
    const float*    A  = (LAYER == 0) ? X : g_h;
    const unsigned* Wt = (LAYER == 0) ? g_wtf1 : g_wtf2;

    extern __shared__ unsigned smem_u[];
    unsigned* Ws  = smem_u;                    // [128 k][WS_PITCH] tf32 W
    unsigned* Ast = smem_u + 128 * WS_PITCH;   // [8][WS_PITCH] tf32 A^T per k-step
    unsigned mbar = (unsigned)__cvta_generic_to_shared(smem_u + GEMM_SMEM_WORDS);

    const int tid  = threadIdx.x;   // 256
    const int lane = tid & 31;
    const int w    = tid >> 5;      // warp 0..7
    const int g    = lane >> 2;     // group 0..7
    const int t    = lane & 3;      // thread-in-group 0..3
    const int row0 = blockIdx.x * GEMM_ROWS;

    // ---- kick off bulk W copy (single thread; no LSU traffic) ----
    if (tid == 0) {
        asm volatile("mbarrier.init.shared::cta.b64 [%0], %1;"
                     :: "r"(mbar), "r"(1) : "memory");
        asm volatile("mbarrier.arrive.expect_tx.shared::cta.b64 _, [%0], %1;"
                     :: "r"(mbar), "r"((unsigned)W_BYTES) : "memory");
        unsigned ws_addr = (unsigned)__cvta_generic_to_shared(Ws);
        asm volatile(
            "cp.async.bulk.shared::cta.global.mbarrier::complete_tx::bytes "
            "[%0], [%1], %2, [%3];"
            :: "r"(ws_addr), "l"(Wt), "r"((unsigned)W_BYTES), "r"(mbar)
            : "memory");
    }

    float acc[16][4];
#pragma unroll
    for (int j = 0; j < 16; j++)
#pragma unroll
        for (int c = 0; c < 4; c++) acc[j][c] = 0.f;

    // ---- main K loop: 16 steps of k=8 ----
    for (int ks = 0; ks < 16; ks++) {
        const int k0 = ks * 8;
        // stage A^T tile: Ast[c][r] = tf32(A[row0+r][k0+c])  (RNA cvt)
        {
            int r = tid >> 1;
            int c4 = (tid & 1) << 2;
            int grow = row0 + r;
            float4 av = make_float4(0.f, 0.f, 0.f, 0.f);
            if (grow < M)
                av = *reinterpret_cast<const float4*>(A + (size_t)grow * HIDD + k0 + c4);
            Ast[(c4 + 0) * WS_PITCH + r] = f2tf32(av.x);
            Ast[(c4 + 1) * WS_PITCH + r] = f2tf32(av.y);
            Ast[(c4 + 2) * WS_PITCH + r] = f2tf32(av.z);
            Ast[(c4 + 3) * WS_PITCH + r] = f2tf32(av.w);
        }
        __syncthreads();          // also makes mbar init visible (ks==0)
        if (ks == 0) mbar_wait0(mbar);   // W bulk copy complete

        unsigned a0 = Ast[t * WS_PITCH + 16 * w + g];
        unsigned a1 = Ast[t * WS_PITCH + 16 * w + g + 8];
        unsigned a2 = Ast[(t + 4) * WS_PITCH + 16 * w + g];
        unsigned a3 = Ast[(t + 4) * WS_PITCH + 16 * w + g + 8];
        const unsigned* wb0 = Ws + (k0 + t) * WS_PITCH + g;
        const unsigned* wb1 = Ws + (k0 + t + 4) * WS_PITCH + g;
#pragma unroll
        for (int j = 0; j < 16; j++) {
            unsigned b0 = wb0[8 * j];
            unsigned b1 = wb1[8 * j];
            mma_tf32(acc[j][0], acc[j][1], acc[j][2], acc[j][3],
                     a0, a1, a2, a3, b0, b1);
        }
        __syncthreads();
    }

    // ---- epilogue: fp16 store + per-head logits ----
    const int rw = row0 + 16 * w;
#pragma unroll
    for (int j = 0; j < 16; j++) {
        float c0 = acc[j][0], c1 = acc[j][1], c2 = acc[j][2], c3 = acc[j][3];
        int colb = 8 * j + 2 * t;
        float2 sv = __ldg(reinterpret_cast<const float2*>(a_src + colb));
        float2 dv = __ldg(reinterpret_cast<const float2*>(a_dst + colb));
        float s0 = c0 * sv.x + c1 * sv.y;
        float d0 = c0 * dv.x + c1 * dv.y;
        float s1 = c2 * sv.x + c3 * sv.y;
        float d1 = c2 * dv.x + c3 * dv.y;
        s0 += __shfl_xor_sync(0xffffffffu, s0, 1);
        s0 += __shfl_xor_sync(0xffffffffu, s0, 2);
        d0 += __shfl_xor_sync(0xffffffffu, d0, 1);
        d0 += __shfl_xor_sync(0xffffffffu, d0, 2);
        s1 += __shfl_xor_sync(0xffffffffu, s1, 1);
        s1 += __shfl_xor_sync(0xffffffffu, s1, 2);
        d1 += __shfl_xor_sync(0xffffffffu, d1, 1);
        d1 += __shfl_xor_sync(0xffffffffu, d1, 2);

        int r0v = rw + g, r1v = rw + g + 8;
        if (r0v < M) {
            __half2 p = __floats2half2_rn(c0, c1);
            *reinterpret_cast<__half2*>(g_xh16 + (size_t)r0v * HIDD + colb) = p;
            if (t == 0) {
                g_als[r0v * HEADS + j] = s0;
                g_ald[r0v * HEADS + j] = d0;
            }
        }
        if (r1v < M) {
            __half2 p = __floats2half2_rn(c2, c3);
            *reinterpret_cast<__half2*>(g_xh16 + (size_t)r1v * HIDD + colb) = p;
            if (t == 0) {
                g_als[r1v * HEADS + j] = s1;
                g_ald[r1v * HEADS + j] = d1;
            }
        }
    }
}

// ---------------- fused aggregation (R8 version — best measured) -----------
__device__ __forceinline__ void load_msg8(const __half* p, float* f) {
    uint4 raw = __ldg(reinterpret_cast<const uint4*>(p));
    const __half2* h = reinterpret_cast<const __half2*>(&raw);
#pragma unroll
    for (int i = 0; i < 4; i++) {
        float2 v = __half22float2(h[i]);
        f[2 * i]     = v.x;
        f[2 * i + 1] = v.y;
    }
}

template <int LAYER>
__global__ void aggregate_kernel(const float* __restrict__ bias,
                                 float* __restrict__ outbuf) {
    const int warp = (blockIdx.x * blockDim.x + threadIdx.x) >> 5;
    if (warp >= NN) return;
    const int lane = threadIdx.x & 31;
    const int hl   = lane & 15;
    const int odd  = lane >> 4;
    const int n = warp;

    const float ald_h = __ldg(g_ald + n * HEADS + hl);

    float acc[8];
    float denom;

    {
        float v = __ldg(g_als + n * HEADS + hl) + ald_h;
        float lr = v > 0.f ? v : 0.2f * v;
        float ex = odd ? 0.f : __expf(lr);
        float f[8];
        load_msg8(g_xh16 + (size_t)n * HIDD + hl * 8, f);
#pragma unroll
        for (int i = 0; i < 8; i++) acc[i] = ex * f[i];
        denom = ex;
    }

    const int beg = __ldg(g_off + n);
    const int end = __ldg(g_off + n + 1);
    const int deg = end - beg;

    for (int j0 = 0; j0 < deg; j0 += 32) {
        int myidx = beg + j0 + lane;
        int s = (myidx < end) ? __ldg(g_srclist + myidx) : 0;
        int cnt = min(32, deg - j0);
#pragma unroll 4
        for (int k = 0; k < cnt; k += 2) {
            int pick = k + odd;
            int src = __shfl_sync(0xffffffffu, s, pick & 31);
            bool valid = pick < cnt;
            float v = __ldg(g_als + src * HEADS + hl) + ald_h;
            float lr = v > 0.f ? v : 0.2f * v;
            float ex = valid ? __expf(lr) : 0.f;
            float f[8];
            load_msg8(g_xh16 + (size_t)src * HIDD + hl * 8, f);
#pragma unroll
            for (int i = 0; i < 8; i++) acc[i] = fmaf(ex, f[i], acc[i]);
            denom += ex;
        }
    }

#pragma unroll
    for (int i = 0; i < 8; i++)
        acc[i] += __shfl_down_sync(0xffffffffu, acc[i], 16);
    denom += __shfl_down_sync(0xffffffffu, denom, 16);

    if (!odd) {
        float inv = 1.f / (denom + 1e-16f);
        float4 b0 = *reinterpret_cast<const float4*>(bias + hl * 8);
        float4 b1 = *reinterpret_cast<const float4*>(bias + hl * 8 + 4);
        float4 r0, r1;
        r0.x = acc[0] * inv + b0.x;
        r0.y = acc[1] * inv + b0.y;
        r0.z = acc[2] * inv + b0.z;
        r0.w = acc[3] * inv + b0.w;
        r1.x = acc[4] * inv + b1.x;
        r1.y = acc[5] * inv + b1.y;
        r1.z = acc[6] * inv + b1.z;
        r1.w = acc[7] * inv + b1.w;
        if (LAYER == 0) {
            r0.x = r0.x > 0.f ? r0.x : expm1f(r0.x);
            r0.y = r0.y > 0.f ? r0.y : expm1f(r0.y);
            r0.z = r0.z > 0.f ? r0.z : expm1f(r0.z);
            r0.w = r0.w > 0.f ? r0.w : expm1f(r0.w);
            r1.x = r1.x > 0.f ? r1.x : expm1f(r1.x);
            r1.y = r1.y > 0.f ? r1.y : expm1f(r1.y);
            r1.z = r1.z > 0.f ? r1.z : expm1f(r1.z);
            r1.w = r1.w > 0.f ? r1.w : expm1f(r1.w);
            *reinterpret_cast<float4*>(g_h + (size_t)n * HIDD + hl * 8)     = r0;
            *reinterpret_cast<float4*>(g_h + (size_t)n * HIDD + hl * 8 + 4) = r1;
        } else {
            *reinterpret_cast<float4*>(outbuf + (size_t)n * HIDD + hl * 8)     = r0;
            *reinterpret_cast<float4*>(outbuf + (size_t)n * HIDD + hl * 8 + 4) = r1;
        }
    }
}

// ---------------- launch ------------------------------------------------------
extern "C" void kernel_launch(void* const* d_in, const int* in_sizes, int n_in,
                              void* d_out, int out_size) {
    const float* x   = (const float*)d_in[0];
    const int*   ei  = (const int*)d_in[1];
    const float* W1  = (const float*)d_in[2];
    const float* as1 = (const float*)d_in[3];
    const float* ad1 = (const float*)d_in[4];
    const float* b1  = (const float*)d_in[5];
    const float* W2  = (const float*)d_in[6];
    const float* as2 = (const float*)d_in[7];
    const float* ad2 = (const float*)d_in[8];
    const float* b2  = (const float*)d_in[9];
    float* out = (float*)d_out;

    cudaFuncSetAttribute(gemm_kernel<0>, cudaFuncAttributeMaxDynamicSharedMemorySize,
                         GEMM_SMEM_BYTES);
    cudaFuncSetAttribute(gemm_kernel<1>, cudaFuncAttributeMaxDynamicSharedMemorySize,
                         GEMM_SMEM_BYTES);

    const int TB = 256;
    const int gGemm = (NN + GEMM_ROWS - 1) / GEMM_ROWS;   // 391
    const int gEdge = (E0C + TB - 1) / TB;
    const int gAgg  = (NN * 32 + TB - 1) / TB;            // one warp per node
    const int gW    = (HIDD * HIDD + TB - 1) / TB;

    // ---- one-time W convert+swizzle + CSR build ----
    wconv_kernel<<<gW, TB>>>(W1, W2);
    csr_hist_kernel<<<gEdge, TB>>>(ei);
    csr_scan_kernel<<<1, 1024>>>();
    csr_scatter_kernel<<<gEdge, TB>>>(ei);

    // ---- layer 1 ----
    gemm_kernel<0><<<gGemm, TB, GEMM_SMEM_BYTES>>>(x, as1, ad1, NN);
    aggregate_kernel<0><<<gAgg, TB>>>(b1, nullptr);

    // ---- layer 2 ----
    gemm_kernel<1><<<gGemm, TB, GEMM_SMEM_BYTES>>>(nullptr, as2, ad2, NN);
    aggregate_kernel<1><<<gAgg, TB>>>(b2, out);
}

// round 15
// speedup vs baseline: 1.0558x; 1.0412x over previous
#include <cuda_runtime.h>
#include <cuda_fp16.h>

// Problem constants (fixed by the dataset)
#define NN    50000
#define E0C   800000
#define HEADS 16
#define HD    8
#define HIDD  128

// ---------------- scratch (device globals, no allocation) ----------------
__device__ __align__(16) __half g_xh16[NN * HIDD];  // fp16 copy of x @ W (message path)
__device__ __align__(16) float  g_h[NN * HIDD];     // layer-1 output (layer-2 input)
__device__ __align__(16) float  g_als[NN * HEADS];
__device__ __align__(16) float  g_ald[NN * HEADS];

// CSR (by dst), built once per call
__device__ int g_deg[NN];
__device__ int g_off[NN + 1];
__device__ int g_cur[NN];
__device__ int g_srclist[E0C];

// ---------------- CSR build -------------------------------------------------
__global__ void csr_zero_kernel() {
    int n = blockIdx.x * blockDim.x + threadIdx.x;
    if (n < NN) g_deg[n] = 0;
}

__global__ void csr_hist_kernel(const int* __restrict__ ei) {
    int e = blockIdx.x * blockDim.x + threadIdx.x;
    if (e >= E0C) return;
    atomicAdd(&g_deg[__ldg(ei + E0C + e)], 1);
}

// single-block exclusive scan over NN degrees
__global__ void csr_scan_kernel() {
    __shared__ int partial[1024];
    const int t = threadIdx.x;
    const int CH = (NN + 1023) / 1024;   // 49
    const int start = t * CH;

    int sum = 0;
    for (int i = 0; i < CH; i++) {
        int n = start + i;
        if (n < NN) sum += g_deg[n];
    }
    partial[t] = sum;
    __syncthreads();
    for (int off = 1; off < 1024; off <<= 1) {
        int v = (t >= off) ? partial[t - off] : 0;
        __syncthreads();
        partial[t] += v;
        __syncthreads();
    }
    int run = (t == 0) ? 0 : partial[t - 1];
    for (int i = 0; i < CH; i++) {
        int n = start + i;
        if (n < NN) {
            g_off[n] = run;
            g_cur[n] = run;
            run += g_deg[n];
        }
    }
    if (t == 1023) g_off[NN] = run;
}

__global__ void csr_scatter_kernel(const int* __restrict__ ei) {
    int e = blockIdx.x * blockDim.x + threadIdx.x;
    if (e >= E0C) return;
    int src = __ldg(ei + e);
    int dst = __ldg(ei + E0C + e);
    int pos = atomicAdd(&g_cur[dst], 1);
    g_srclist[pos] = src;
}

// ---------------- tf32 tensor-core GEMM + fused logits + fp16 store --------
#define WS_PITCH 136   // words; 136 % 32 == 8 -> conflict-free frag loads
#define GEMM_ROWS 128
#define GEMM_SMEM_BYTES ((128 * WS_PITCH + 8 * WS_PITCH) * 4)

__device__ __forceinline__ unsigned f2tf32(float f) {
    unsigned r;
    asm("cvt.rna.tf32.f32 %0, %1;" : "=r"(r) : "f"(f));
    return r;
}

__device__ __forceinline__ void mma_tf32(float& d0, float& d1, float& d2, float& d3,
                                         unsigned a0, unsigned a1, unsigned a2, unsigned a3,
                                         unsigned b0, unsigned b1) {
    asm volatile(
        "mma.sync.aligned.m16n8k8.row.col.f32.tf32.tf32.f32 "
        "{%0,%1,%2,%3},{%4,%5,%6,%7},{%8,%9},{%0,%1,%2,%3};"
        : "+f"(d0), "+f"(d1), "+f"(d2), "+f"(d3)
        : "r"(a0), "r"(a1), "r"(a2), "r"(a3), "r"(b0), "r"(b1));
}

template <int LAYER>
__global__ void gemm_kernel(const float* __restrict__ X,
                            const float* __restrict__ W,
                            const float* __restrict__ a_src,
                            const float* __restrict__ a_dst, int M) {
    const float* A = (LAYER == 0) ? X : g_h;

    extern __shared__ unsigned smem_u[];
    unsigned* Ws  = smem_u;                    // [128][WS_PITCH] tf32 W (k-major)
    unsigned* Ast = smem_u + 128 * WS_PITCH;   // [8][WS_PITCH] tf32 A^T per k-step

    const int tid  = threadIdx.x;   // 256
    const int lane = tid & 31;
    const int w    = tid >> 5;      // warp 0..7
    const int g    = lane >> 2;     // group 0..7
    const int t    = lane & 3;      // thread-in-group 0..3
    const int row0 = blockIdx.x * GEMM_ROWS;

    // ---- stage W (convert to tf32), 16 float4 per thread ----
#pragma unroll
    for (int it = 0; it < 16; it++) {
        int v = tid + it * 256;
        int k = v >> 5;
        int n4 = (v & 31) << 2;
        float4 wv = *reinterpret_cast<const float4*>(W + (size_t)k * HIDD + n4);
        unsigned* p = Ws + k * WS_PITCH + n4;
        p[0] = f2tf32(wv.x); p[1] = f2tf32(wv.y);
        p[2] = f2tf32(wv.z); p[3] = f2tf32(wv.w);
    }
    __syncthreads();

    float acc[16][4];
#pragma unroll
    for (int j = 0; j < 16; j++)
#pragma unroll
        for (int c = 0; c < 4; c++) acc[j][c] = 0.f;

    // ---- main K loop: 16 steps of k=8 ----
    for (int ks = 0; ks < 16; ks++) {
        const int k0 = ks * 8;
        {
            int r = tid >> 1;
            int c4 = (tid & 1) << 2;
            int grow = row0 + r;
            float4 av = make_float4(0.f, 0.f, 0.f, 0.f);
            if (grow < M)
                av = *reinterpret_cast<const float4*>(A + (size_t)grow * HIDD + k0 + c4);
            Ast[(c4 + 0) * WS_PITCH + r] = f2tf32(av.x);
            Ast[(c4 + 1) * WS_PITCH + r] = f2tf32(av.y);
            Ast[(c4 + 2) * WS_PITCH + r] = f2tf32(av.z);
            Ast[(c4 + 3) * WS_PITCH + r] = f2tf32(av.w);
        }
        __syncthreads();

        unsigned a0 = Ast[t * WS_PITCH + 16 * w + g];
        unsigned a1 = Ast[t * WS_PITCH + 16 * w + g + 8];
        unsigned a2 = Ast[(t + 4) * WS_PITCH + 16 * w + g];
        unsigned a3 = Ast[(t + 4) * WS_PITCH + 16 * w + g + 8];
        const unsigned* wb0 = Ws + (k0 + t) * WS_PITCH + g;
        const unsigned* wb1 = Ws + (k0 + t + 4) * WS_PITCH + g;
#pragma unroll
        for (int j = 0; j < 16; j++) {
            unsigned b0 = wb0[8 * j];
            unsigned b1 = wb1[8 * j];
            mma_tf32(acc[j][0], acc[j][1], acc[j][2], acc[j][3],
                     a0, a1, a2, a3, b0, b1);
        }
        __syncthreads();
    }

    // ---- epilogue: fp16 store + per-head logits ----
    const int rw = row0 + 16 * w;
#pragma unroll
    for (int j = 0; j < 16; j++) {
        float c0 = acc[j][0], c1 = acc[j][1], c2 = acc[j][2], c3 = acc[j][3];
        int colb = 8 * j + 2 * t;
        float2 sv = __ldg(reinterpret_cast<const float2*>(a_src + colb));
        float2 dv = __ldg(reinterpret_cast<const float2*>(a_dst + colb));
        float s0 = c0 * sv.x + c1 * sv.y;
        float d0 = c0 * dv.x + c1 * dv.y;
        float s1 = c2 * sv.x + c3 * sv.y;
        float d1 = c2 * dv.x + c3 * dv.y;
        s0 += __shfl_xor_sync(0xffffffffu, s0, 1);
        s0 += __shfl_xor_sync(0xffffffffu, s0, 2);
        d0 += __shfl_xor_sync(0xffffffffu, d0, 1);
        d0 += __shfl_xor_sync(0xffffffffu, d0, 2);
        s1 += __shfl_xor_sync(0xffffffffu, s1, 1);
        s1 += __shfl_xor_sync(0xffffffffu, s1, 2);
        d1 += __shfl_xor_sync(0xffffffffu, d1, 1);
        d1 += __shfl_xor_sync(0xffffffffu, d1, 2);

        int r0v = rw + g, r1v = rw + g + 8;
        if (r0v < M) {
            __half2 p = __floats2half2_rn(c0, c1);
            *reinterpret_cast<__half2*>(g_xh16 + (size_t)r0v * HIDD + colb) = p;
            if (t == 0) {
                g_als[r0v * HEADS + j] = s0;
                g_ald[r0v * HEADS + j] = d0;
            }
        }
        if (r1v < M) {
            __half2 p = __floats2half2_rn(c2, c3);
            *reinterpret_cast<__half2*>(g_xh16 + (size_t)r1v * HIDD + colb) = p;
            if (t == 0) {
                g_als[r1v * HEADS + j] = s1;
                g_ald[r1v * HEADS + j] = d1;
            }
        }
    }
}

// ---------------- fused aggregation: half-warp per neighbor ----------------
__device__ __forceinline__ void load_msg8(const __half* p, float* f) {
    uint4 raw = __ldg(reinterpret_cast<const uint4*>(p));
    const __half2* h = reinterpret_cast<const __half2*>(&raw);
#pragma unroll
    for (int i = 0; i < 4; i++) {
        float2 v = __half22float2(h[i]);
        f[2 * i]     = v.x;
        f[2 * i + 1] = v.y;
    }
}

template <int LAYER>
__global__ void aggregate_kernel(const float* __restrict__ bias,
                                 float* __restrict__ outbuf) {
    const int warp = (blockIdx.x * blockDim.x + threadIdx.x) >> 5;
    if (warp >= NN) return;
    const int lane = threadIdx.x & 31;
    const int hl   = lane & 15;        // head owned by this lane
    const int odd  = lane >> 4;        // 0: even neighbors, 1: odd neighbors
    const int n = warp;

    const float ald_h = __ldg(g_ald + n * HEADS + hl);

    float acc[8];
    float denom;

    // self loop: group A only
    {
        float v = __ldg(g_als + n * HEADS + hl) + ald_h;
        float lr = v > 0.f ? v : 0.2f * v;
        float ex = odd ? 0.f : __expf(lr);
        float f[8];
        load_msg8(g_xh16 + (size_t)n * HIDD + hl * 8, f);
#pragma unroll
        for (int i = 0; i < 8; i++) acc[i] = ex * f[i];
        denom = ex;
    }

    const int beg = __ldg(g_off + n);
    const int end = __ldg(g_off + n + 1);
    const int deg = end - beg;

    for (int j0 = 0; j0 < deg; j0 += 32) {
        int myidx = beg + j0 + lane;
        int s = (myidx < end) ? __ldg(g_srclist + myidx) : 0;
        int cnt = min(32, deg - j0);
#pragma unroll 4
        for (int k = 0; k < cnt; k += 2) {
            int pick = k + odd;
            int src = __shfl_sync(0xffffffffu, s, pick & 31);
            bool valid = pick < cnt;
            float v = __ldg(g_als + src * HEADS + hl) + ald_h;
            float lr = v > 0.f ? v : 0.2f * v;
            float ex = valid ? __expf(lr) : 0.f;
            float f[8];
            load_msg8(g_xh16 + (size_t)src * HIDD + hl * 8, f);
#pragma unroll
            for (int i = 0; i < 8; i++) acc[i] = fmaf(ex, f[i], acc[i]);
            denom += ex;
        }
    }

#pragma unroll
    for (int i = 0; i < 8; i++)
        acc[i] += __shfl_down_sync(0xffffffffu, acc[i], 16);
    denom += __shfl_down_sync(0xffffffffu, denom, 16);

    if (!odd) {
        float inv = 1.f / (denom + 1e-16f);
        float4 b0 = *reinterpret_cast<const float4*>(bias + hl * 8);
        float4 b1 = *reinterpret_cast<const float4*>(bias + hl * 8 + 4);
        float4 r0, r1;
        r0.x = acc[0] * inv + b0.x;
        r0.y = acc[1] * inv + b0.y;
        r0.z = acc[2] * inv + b0.z;
        r0.w = acc[3] * inv + b0.w;
        r1.x = acc[4] * inv + b1.x;
        r1.y = acc[5] * inv + b1.y;
        r1.z = acc[6] * inv + b1.z;
        r1.w = acc[7] * inv + b1.w;
        if (LAYER == 0) {
            r0.x = r0.x > 0.f ? r0.x : expm1f(r0.x);
            r0.y = r0.y > 0.f ? r0.y : expm1f(r0.y);
            r0.z = r0.z > 0.f ? r0.z : expm1f(r0.z);
            r0.w = r0.w > 0.f ? r0.w : expm1f(r0.w);
            r1.x = r1.x > 0.f ? r1.x : expm1f(r1.x);
            r1.y = r1.y > 0.f ? r1.y : expm1f(r1.y);
            r1.z = r1.z > 0.f ? r1.z : expm1f(r1.z);
            r1.w = r1.w > 0.f ? r1.w : expm1f(r1.w);
            *reinterpret_cast<float4*>(g_h + (size_t)n * HIDD + hl * 8)     = r0;
            *reinterpret_cast<float4*>(g_h + (size_t)n * HIDD + hl * 8 + 4) = r1;
        } else {
            *reinterpret_cast<float4*>(outbuf + (size_t)n * HIDD + hl * 8)     = r0;
            *reinterpret_cast<float4*>(outbuf + (size_t)n * HIDD + hl * 8 + 4) = r1;
        }
    }
}

// ---------------- launch ------------------------------------------------------
// CSR build runs on a side stream, concurrent with gemm<0> (independent work);
// fork/join via events (graph-capture-legal pattern). Stream/events created
// once on the first (uncaptured) call; captured calls replay identical nodes.
extern "C" void kernel_launch(void* const* d_in, const int* in_sizes, int n_in,
                              void* d_out, int out_size) {
    const float* x   = (const float*)d_in[0];
    const int*   ei  = (const int*)d_in[1];
    const float* W1  = (const float*)d_in[2];
    const float* as1 = (const float*)d_in[3];
    const float* ad1 = (const float*)d_in[4];
    const float* b1  = (const float*)d_in[5];
    const float* W2  = (const float*)d_in[6];
    const float* as2 = (const float*)d_in[7];
    const float* ad2 = (const float*)d_in[8];
    const float* b2  = (const float*)d_in[9];
    float* out = (float*)d_out;

    static cudaStream_t s2 = nullptr;
    static cudaEvent_t evFork = nullptr, evJoin = nullptr;
    if (s2 == nullptr) {
        cudaStreamCreateWithFlags(&s2, cudaStreamNonBlocking);
        cudaEventCreateWithFlags(&evFork, cudaEventDisableTiming);
        cudaEventCreateWithFlags(&evJoin, cudaEventDisableTiming);
    }

    cudaFuncSetAttribute(gemm_kernel<0>, cudaFuncAttributeMaxDynamicSharedMemorySize,
                         GEMM_SMEM_BYTES);
    cudaFuncSetAttribute(gemm_kernel<1>, cudaFuncAttributeMaxDynamicSharedMemorySize,
                         GEMM_SMEM_BYTES);

    const int TB = 256;
    const int gGemm = (NN + GEMM_ROWS - 1) / GEMM_ROWS;
    const int gEdge = (E0C + TB - 1) / TB;
    const int gNode = (NN + TB - 1) / TB;
    const int gAgg  = (NN * 32 + TB - 1) / TB;   // one warp per node

    // ---- fork: CSR build on s2, gemm<0> on main stream (independent) ----
    cudaEventRecord(evFork, 0);
    cudaStreamWaitEvent(s2, evFork, 0);

    csr_zero_kernel<<<gNode, TB, 0, s2>>>();
    csr_hist_kernel<<<gEdge, TB, 0, s2>>>(ei);
    csr_scan_kernel<<<1, 1024, 0, s2>>>();
    csr_scatter_kernel<<<gEdge, TB, 0, s2>>>(ei);
    cudaEventRecord(evJoin, s2);

    gemm_kernel<0><<<gGemm, TB, GEMM_SMEM_BYTES>>>(x, W1, as1, ad1, NN);

    // ---- join: aggregate<0> needs both CSR and gemm<0> ----
    cudaStreamWaitEvent(0, evJoin, 0);
    aggregate_kernel<0><<<gAgg, TB>>>(b1, nullptr);

    // ---- layer 2 (sequential dependencies) ----
    gemm_kernel<1><<<gGemm, TB, GEMM_SMEM_BYTES>>>(nullptr, W2, as2, ad2, NN);
    aggregate_kernel<1><<<gAgg, TB>>>(b2, out);
}

// round 16
// speedup vs baseline: 1.0808x; 1.0237x over previous
#include <cuda_runtime.h>
#include <cuda_fp16.h>

// Problem constants (fixed by the dataset)
#define NN    50000
#define E0C   800000
#define HEADS 16
#define HD    8
#define HIDD  128

// ---------------- scratch (device globals, no allocation) ----------------
__device__ __align__(16) __half g_xh16[NN * HIDD];  // fp16 copy of x @ W (message path)
__device__ __align__(16) float  g_h[NN * HIDD];     // layer-1 output (layer-2 input)
__device__ __align__(16) float  g_als[NN * HEADS];
__device__ __align__(16) float  g_ald[NN * HEADS];

// CSR (by dst), built once per call.
// INVARIANT: g_deg all-zero on entry (zero-init at load; csr_scan re-zeroes).
__device__ int g_deg[NN];
__device__ int g_off[NN + 1];
__device__ int g_cur[NN];
__device__ int g_srclist[E0C];

// ---------------- CSR build -------------------------------------------------
__global__ void csr_hist_kernel(const int* __restrict__ ei) {
    int e = blockIdx.x * blockDim.x + threadIdx.x;
    if (e >= E0C) return;
    atomicAdd(&g_deg[__ldg(ei + E0C + e)], 1);
}

// single-block exclusive scan over NN degrees; re-zeros g_deg afterwards
__global__ void csr_scan_kernel() {
    __shared__ int partial[1024];
    const int t = threadIdx.x;
    const int CH = (NN + 1023) / 1024;   // 49
    const int start = t * CH;

    int sum = 0;
    for (int i = 0; i < CH; i++) {
        int n = start + i;
        if (n < NN) sum += g_deg[n];
    }
    partial[t] = sum;
    __syncthreads();
    for (int off = 1; off < 1024; off <<= 1) {
        int v = (t >= off) ? partial[t - off] : 0;
        __syncthreads();
        partial[t] += v;
        __syncthreads();
    }
    int run = (t == 0) ? 0 : partial[t - 1];
    for (int i = 0; i < CH; i++) {
        int n = start + i;
        if (n < NN) {
            int d = g_deg[n];
            g_off[n] = run;
            g_cur[n] = run;
            run += d;
            g_deg[n] = 0;   // restore invariant for next call
        }
    }
    if (t == 1023) g_off[NN] = run;
}

__global__ void csr_scatter_kernel(const int* __restrict__ ei) {
    int e = blockIdx.x * blockDim.x + threadIdx.x;
    if (e >= E0C) return;
    int src = __ldg(ei + e);
    int dst = __ldg(ei + E0C + e);
    int pos = atomicAdd(&g_cur[dst], 1);
    g_srclist[pos] = src;
}

// ---------------- tf32 tensor-core GEMM + fused logits + fp16 store --------
// (R8 version — best measured; untouched)
#define WS_PITCH 136   // words; 136 % 32 == 8 -> conflict-free frag loads
#define GEMM_ROWS 128
#define GEMM_SMEM_BYTES ((128 * WS_PITCH + 8 * WS_PITCH) * 4)

__device__ __forceinline__ unsigned f2tf32(float f) {
    unsigned r;
    asm("cvt.rna.tf32.f32 %0, %1;" : "=r"(r) : "f"(f));
    return r;
}

__device__ __forceinline__ void mma_tf32(float& d0, float& d1, float& d2, float& d3,
                                         unsigned a0, unsigned a1, unsigned a2, unsigned a3,
                                         unsigned b0, unsigned b1) {
    asm volatile(
        "mma.sync.aligned.m16n8k8.row.col.f32.tf32.tf32.f32 "
        "{%0,%1,%2,%3},{%4,%5,%6,%7},{%8,%9},{%0,%1,%2,%3};"
        : "+f"(d0), "+f"(d1), "+f"(d2), "+f"(d3)
        : "r"(a0), "r"(a1), "r"(a2), "r"(a3), "r"(b0), "r"(b1));
}

template <int LAYER>
__global__ void gemm_kernel(const float* __restrict__ X,
                            const float* __restrict__ W,
                            const float* __restrict__ a_src,
                            const float* __restrict__ a_dst, int M) {
    const float* A = (LAYER == 0) ? X : g_h;

    extern __shared__ unsigned smem_u[];
    unsigned* Ws  = smem_u;                    // [128][WS_PITCH] tf32 W (k-major)
    unsigned* Ast = smem_u + 128 * WS_PITCH;   // [8][WS_PITCH] tf32 A^T per k-step

    const int tid  = threadIdx.x;   // 256
    const int lane = tid & 31;
    const int w    = tid >> 5;      // warp 0..7
    const int g    = lane >> 2;     // group 0..7
    const int t    = lane & 3;      // thread-in-group 0..3
    const int row0 = blockIdx.x * GEMM_ROWS;

#pragma unroll
    for (int it = 0; it < 16; it++) {
        int v = tid + it * 256;
        int k = v >> 5;
        int n4 = (v & 31) << 2;
        float4 wv = *reinterpret_cast<const float4*>(W + (size_t)k * HIDD + n4);
        unsigned* p = Ws + k * WS_PITCH + n4;
        p[0] = f2tf32(wv.x); p[1] = f2tf32(wv.y);
        p[2] = f2tf32(wv.z); p[3] = f2tf32(wv.w);
    }
    __syncthreads();

    float acc[16][4];
#pragma unroll
    for (int j = 0; j < 16; j++)
#pragma unroll
        for (int c = 0; c < 4; c++) acc[j][c] = 0.f;

    for (int ks = 0; ks < 16; ks++) {
        const int k0 = ks * 8;
        {
            int r = tid >> 1;
            int c4 = (tid & 1) << 2;
            int grow = row0 + r;
            float4 av = make_float4(0.f, 0.f, 0.f, 0.f);
            if (grow < M)
                av = *reinterpret_cast<const float4*>(A + (size_t)grow * HIDD + k0 + c4);
            Ast[(c4 + 0) * WS_PITCH + r] = f2tf32(av.x);
            Ast[(c4 + 1) * WS_PITCH + r] = f2tf32(av.y);
            Ast[(c4 + 2) * WS_PITCH + r] = f2tf32(av.z);
            Ast[(c4 + 3) * WS_PITCH + r] = f2tf32(av.w);
        }
        __syncthreads();

        unsigned a0 = Ast[t * WS_PITCH + 16 * w + g];
        unsigned a1 = Ast[t * WS_PITCH + 16 * w + g + 8];
        unsigned a2 = Ast[(t + 4) * WS_PITCH + 16 * w + g];
        unsigned a3 = Ast[(t + 4) * WS_PITCH + 16 * w + g + 8];
        const unsigned* wb0 = Ws + (k0 + t) * WS_PITCH + g;
        const unsigned* wb1 = Ws + (k0 + t + 4) * WS_PITCH + g;
#pragma unroll
        for (int j = 0; j < 16; j++) {
            unsigned b0 = wb0[8 * j];
            unsigned b1 = wb1[8 * j];
            mma_tf32(acc[j][0], acc[j][1], acc[j][2], acc[j][3],
                     a0, a1, a2, a3, b0, b1);
        }
        __syncthreads();
    }

    const int rw = row0 + 16 * w;
#pragma unroll
    for (int j = 0; j < 16; j++) {
        float c0 = acc[j][0], c1 = acc[j][1], c2 = acc[j][2], c3 = acc[j][3];
        int colb = 8 * j + 2 * t;
        float2 sv = __ldg(reinterpret_cast<const float2*>(a_src + colb));
        float2 dv = __ldg(reinterpret_cast<const float2*>(a_dst + colb));
        float s0 = c0 * sv.x + c1 * sv.y;
        float d0 = c0 * dv.x + c1 * dv.y;
        float s1 = c2 * sv.x + c3 * sv.y;
        float d1 = c2 * dv.x + c3 * dv.y;
        s0 += __shfl_xor_sync(0xffffffffu, s0, 1);
        s0 += __shfl_xor_sync(0xffffffffu, s0, 2);
        d0 += __shfl_xor_sync(0xffffffffu, d0, 1);
        d0 += __shfl_xor_sync(0xffffffffu, d0, 2);
        s1 += __shfl_xor_sync(0xffffffffu, s1, 1);
        s1 += __shfl_xor_sync(0xffffffffu, s1, 2);
        d1 += __shfl_xor_sync(0xffffffffu, d1, 1);
        d1 += __shfl_xor_sync(0xffffffffu, d1, 2);

        int r0v = rw + g, r1v = rw + g + 8;
        if (r0v < M) {
            __half2 p = __floats2half2_rn(c0, c1);
            *reinterpret_cast<__half2*>(g_xh16 + (size_t)r0v * HIDD + colb) = p;
            if (t == 0) {
                g_als[r0v * HEADS + j] = s0;
                g_ald[r0v * HEADS + j] = d0;
            }
        }
        if (r1v < M) {
            __half2 p = __floats2half2_rn(c2, c3);
            *reinterpret_cast<__half2*>(g_xh16 + (size_t)r1v * HIDD + colb) = p;
            if (t == 0) {
                g_als[r1v * HEADS + j] = s1;
                g_ald[r1v * HEADS + j] = d1;
            }
        }
    }
}

// ---------------- fused aggregation v3: half-warp per NODE ------------------
// Warp handles nodes 2*warp (lanes 0-15) and 2*warp+1 (lanes 16-31).
// Lane owns head hl = lane&15 (8 output cols). No shuffles, no cross-half
// combine, no odd/even predication: src index is a broadcast load shared by
// the 16 lanes of a half-warp. #pragma unroll 4 front-batches independent
// src loads for MLP.
__device__ __forceinline__ void load_msg8(const __half* p, float* f) {
    uint4 raw = __ldg(reinterpret_cast<const uint4*>(p));
    const __half2* h = reinterpret_cast<const __half2*>(&raw);
#pragma unroll
    for (int i = 0; i < 4; i++) {
        float2 v = __half22float2(h[i]);
        f[2 * i]     = v.x;
        f[2 * i + 1] = v.y;
    }
}

template <int LAYER>
__global__ void aggregate_kernel(const float* __restrict__ bias,
                                 float* __restrict__ outbuf) {
    const int warp = (blockIdx.x * blockDim.x + threadIdx.x) >> 5;
    const int lane = threadIdx.x & 31;
    const int hl   = lane & 15;           // head owned by this lane
    const int n    = warp * 2 + (lane >> 4);   // node for this half-warp
    if (n >= NN) return;

    const float ald_h = __ldg(g_ald + n * HEADS + hl);

    float acc[8];
    float denom;

    // self loop
    {
        float v = __ldg(g_als + n * HEADS + hl) + ald_h;
        float lr = v > 0.f ? v : 0.2f * v;
        float ex = __expf(lr);
        float f[8];
        load_msg8(g_xh16 + (size_t)n * HIDD + hl * 8, f);
#pragma unroll
        for (int i = 0; i < 8; i++) acc[i] = ex * f[i];
        denom = ex;
    }

    const int beg = __ldg(g_off + n);
    const int deg = __ldg(g_off + n + 1) - beg;

#pragma unroll 4
    for (int k = 0; k < deg; k++) {
        int src = __ldg(g_srclist + beg + k);   // broadcast within half-warp
        float v = __ldg(g_als + src * HEADS + hl) + ald_h;
        float lr = v > 0.f ? v : 0.2f * v;
        float ex = __expf(lr);
        float f[8];
        load_msg8(g_xh16 + (size_t)src * HIDD + hl * 8, f);
#pragma unroll
        for (int i = 0; i < 8; i++) acc[i] = fmaf(ex, f[i], acc[i]);
        denom += ex;
    }

    float inv = 1.f / (denom + 1e-16f);
    float4 b0 = *reinterpret_cast<const float4*>(bias + hl * 8);
    float4 b1 = *reinterpret_cast<const float4*>(bias + hl * 8 + 4);
    float4 r0, r1;
    r0.x = acc[0] * inv + b0.x;
    r0.y = acc[1] * inv + b0.y;
    r0.z = acc[2] * inv + b0.z;
    r0.w = acc[3] * inv + b0.w;
    r1.x = acc[4] * inv + b1.x;
    r1.y = acc[5] * inv + b1.y;
    r1.z = acc[6] * inv + b1.z;
    r1.w = acc[7] * inv + b1.w;
    if (LAYER == 0) {
        r0.x = r0.x > 0.f ? r0.x : expm1f(r0.x);
        r0.y = r0.y > 0.f ? r0.y : expm1f(r0.y);
        r0.z = r0.z > 0.f ? r0.z : expm1f(r0.z);
        r0.w = r0.w > 0.f ? r0.w : expm1f(r0.w);
        r1.x = r1.x > 0.f ? r1.x : expm1f(r1.x);
        r1.y = r1.y > 0.f ? r1.y : expm1f(r1.y);
        r1.z = r1.z > 0.f ? r1.z : expm1f(r1.z);
        r1.w = r1.w > 0.f ? r1.w : expm1f(r1.w);
        *reinterpret_cast<float4*>(g_h + (size_t)n * HIDD + hl * 8)     = r0;
        *reinterpret_cast<float4*>(g_h + (size_t)n * HIDD + hl * 8 + 4) = r1;
    } else {
        *reinterpret_cast<float4*>(outbuf + (size_t)n * HIDD + hl * 8)     = r0;
        *reinterpret_cast<float4*>(outbuf + (size_t)n * HIDD + hl * 8 + 4) = r1;
    }
}

// ---------------- launch ------------------------------------------------------
extern "C" void kernel_launch(void* const* d_in, const int* in_sizes, int n_in,
                              void* d_out, int out_size) {
    const float* x   = (const float*)d_in[0];
    const int*   ei  = (const int*)d_in[1];
    const float* W1  = (const float*)d_in[2];
    const float* as1 = (const float*)d_in[3];
    const float* ad1 = (const float*)d_in[4];
    const float* b1  = (const float*)d_in[5];
    const float* W2  = (const float*)d_in[6];
    const float* as2 = (const float*)d_in[7];
    const float* ad2 = (const float*)d_in[8];
    const float* b2  = (const float*)d_in[9];
    float* out = (float*)d_out;

    cudaFuncSetAttribute(gemm_kernel<0>, cudaFuncAttributeMaxDynamicSharedMemorySize,
                         GEMM_SMEM_BYTES);
    cudaFuncSetAttribute(gemm_kernel<1>, cudaFuncAttributeMaxDynamicSharedMemorySize,
                         GEMM_SMEM_BYTES);

    const int TB = 256;
    const int gGemm = (NN + GEMM_ROWS - 1) / GEMM_ROWS;
    const int gEdge = (E0C + TB - 1) / TB;
    const int gAgg  = (NN / 2 * 32 + TB - 1) / TB;   // 2 nodes per warp

    // ---- CSR build (g_deg zero-invariant maintained by csr_scan) ----
    csr_hist_kernel<<<gEdge, TB>>>(ei);
    csr_scan_kernel<<<1, 1024>>>();
    csr_scatter_kernel<<<gEdge, TB>>>(ei);

    // ---- layer 1 ----
    gemm_kernel<0><<<gGemm, TB, GEMM_SMEM_BYTES>>>(x, W1, as1, ad1, NN);
    aggregate_kernel<0><<<gAgg, TB>>>(b1, nullptr);

    // ---- layer 2 ----
    gemm_kernel<1><<<gGemm, TB, GEMM_SMEM_BYTES>>>(nullptr, W2, as2, ad2, NN);
    aggregate_kernel<1><<<gAgg, TB>>>(b2, out);
}

// round 17
// speedup vs baseline: 1.1516x; 1.0655x over previous
#include <cuda_runtime.h>
#include <cuda_fp16.h>

// Problem constants (fixed by the dataset)
#define NN    50000
#define E0C   800000
#define HEADS 16
#define HD    8
#define HIDD  128

// ---------------- scratch (device globals, no allocation) ----------------
__device__ __align__(16) __half g_xh16[NN * HIDD];  // fp16 copy of x @ W (message path)
__device__ __align__(16) float  g_h[NN * HIDD];     // layer-1 output (layer-2 input)
__device__ __align__(16) float  g_als[NN * HEADS];
__device__ __align__(16) float  g_ald[NN * HEADS];

// CSR (by dst), built once per call.
// INVARIANT: g_deg all-zero on entry (zero-init at load; csr_scan re-zeroes).
__device__ int g_deg[NN];
__device__ int g_off[NN + 1];
__device__ int g_cur[NN];
__device__ int g_srclist[E0C];

// ---------------- CSR build -------------------------------------------------
__global__ void csr_hist_kernel(const int* __restrict__ ei) {
    int e = blockIdx.x * blockDim.x + threadIdx.x;
    if (e >= E0C) return;
    atomicAdd(&g_deg[__ldg(ei + E0C + e)], 1);
}

// single-block exclusive scan over NN degrees; re-zeros g_deg afterwards
__global__ void csr_scan_kernel() {
    __shared__ int partial[1024];
    const int t = threadIdx.x;
    const int CH = (NN + 1023) / 1024;   // 49
    const int start = t * CH;

    int sum = 0;
    for (int i = 0; i < CH; i++) {
        int n = start + i;
        if (n < NN) sum += g_deg[n];
    }
    partial[t] = sum;
    __syncthreads();
    for (int off = 1; off < 1024; off <<= 1) {
        int v = (t >= off) ? partial[t - off] : 0;
        __syncthreads();
        partial[t] += v;
        __syncthreads();
    }
    int run = (t == 0) ? 0 : partial[t - 1];
    for (int i = 0; i < CH; i++) {
        int n = start + i;
        if (n < NN) {
            int d = g_deg[n];
            g_off[n] = run;
            g_cur[n] = run;
            run += d;
            g_deg[n] = 0;   // restore invariant for next call
        }
    }
    if (t == 1023) g_off[NN] = run;
}

__global__ void csr_scatter_kernel(const int* __restrict__ ei) {
    int e = blockIdx.x * blockDim.x + threadIdx.x;
    if (e >= E0C) return;
    int src = __ldg(ei + e);
    int dst = __ldg(ei + E0C + e);
    int pos = atomicAdd(&g_cur[dst], 1);
    g_srclist[pos] = src;
}

// ---------------- tf32 tensor-core GEMM v5: cp.async pipelined A -----------
// 128 rows/block, 8 warps (16 rows each), 16 j-tiles per warp (R8 mapping).
// W staged once (LDG+cvt+STS, as R8). A staged RAW fp32 row-major into a
// 4-deep ring of 128x16 tiles via cp.async.cg; tf32 cvt happens in registers
// after LDS. While stage st computes, stages st+1..st+3 are in flight.
#define WS_PITCH 136   // words; 136 % 32 == 8 -> conflict-free B-frag loads
#define A_P      20    // words/row; (20g+t) mod 32 distinct -> conflict-free
#define STAGE_COLS 16  // two k-steps per stage
#define N_STAGES 8     // 128 / 16
#define PIPE 4
#define STAGE_WORDS (128 * A_P)          // 2560
#define GEMM_ROWS 128
#define GEMM_SMEM_BYTES ((128 * WS_PITCH + PIPE * STAGE_WORDS) * 4)  // 110,592

__device__ __forceinline__ unsigned f2tf32(float f) {
    unsigned r;
    asm("cvt.rna.tf32.f32 %0, %1;" : "=r"(r) : "f"(f));
    return r;
}

__device__ __forceinline__ void mma_tf32(float& d0, float& d1, float& d2, float& d3,
                                         unsigned a0, unsigned a1, unsigned a2, unsigned a3,
                                         unsigned b0, unsigned b1) {
    asm volatile(
        "mma.sync.aligned.m16n8k8.row.col.f32.tf32.tf32.f32 "
        "{%0,%1,%2,%3},{%4,%5,%6,%7},{%8,%9},{%0,%1,%2,%3};"
        : "+f"(d0), "+f"(d1), "+f"(d2), "+f"(d3)
        : "r"(a0), "r"(a1), "r"(a2), "r"(a3), "r"(b0), "r"(b1));
}

template <int N>
__device__ __forceinline__ void cp_async_wait() {
    asm volatile("cp.async.wait_group %0;" :: "n"(N) : "memory");
}

template <int LAYER>
__global__ void gemm_kernel(const float* __restrict__ X,
                            const float* __restrict__ W,
                            const float* __restrict__ a_src,
                            const float* __restrict__ a_dst, int M) {
    const float* A = (LAYER == 0) ? X : g_h;

    extern __shared__ unsigned smem_u[];
    unsigned* Ws   = smem_u;                     // [128][WS_PITCH] tf32 W
    float*    Abuf = (float*)(smem_u + 128 * WS_PITCH);  // [PIPE][128][A_P] raw fp32

    const int tid  = threadIdx.x;   // 256
    const int lane = tid & 31;
    const int w    = tid >> 5;      // warp 0..7
    const int g    = lane >> 2;     // group 0..7
    const int t    = lane & 3;      // thread-in-group 0..3
    const int row0 = blockIdx.x * GEMM_ROWS;

    // per-thread cp.async source/dest (2 chunks of 16B per stage)
    const int arow = tid >> 2;          // 0..63  (chunk 0) / +64 (chunk 1)
    const int aq   = tid & 3;           // col quarter (x4 floats)

    // issue one stage of A copies
    auto issue_stage = [&](int s) {
#pragma unroll
        for (int i = 0; i < 2; i++) {
            int r = arow + i * 64;
            int grow = row0 + r;
            const float* src = A + (size_t)((grow < M) ? grow : row0) * HIDD
                               + s * STAGE_COLS + aq * 4;
            unsigned sz = (grow < M) ? 16u : 0u;
            unsigned dst = (unsigned)__cvta_generic_to_shared(
                Abuf + (s & 3) * STAGE_WORDS + r * A_P + aq * 4);
            asm volatile("cp.async.cg.shared.global [%0], [%1], 16, %2;"
                         :: "r"(dst), "l"(src), "r"(sz) : "memory");
        }
        asm volatile("cp.async.commit_group;" ::: "memory");
    };

    // kick off the pipeline
#pragma unroll
    for (int s = 0; s < PIPE; s++) issue_stage(s);

    // ---- stage W (convert to tf32), 16 float4 per thread ----
#pragma unroll
    for (int it = 0; it < 16; it++) {
        int v = tid + it * 256;
        int k = v >> 5;
        int n4 = (v & 31) << 2;
        float4 wv = *reinterpret_cast<const float4*>(W + (size_t)k * HIDD + n4);
        unsigned* p = Ws + k * WS_PITCH + n4;
        p[0] = f2tf32(wv.x); p[1] = f2tf32(wv.y);
        p[2] = f2tf32(wv.z); p[3] = f2tf32(wv.w);
    }

    float acc[16][4];
#pragma unroll
    for (int j = 0; j < 16; j++)
#pragma unroll
        for (int c = 0; c < 4; c++) acc[j][c] = 0.f;

    // ---- main loop over 8 stages (2 k-steps each) ----
    for (int st = 0; st < N_STAGES; st++) {
        // wait for stage st's data (exact immediates per remaining depth)
        if (st < 5)      cp_async_wait<3>();
        else if (st == 5) cp_async_wait<2>();
        else if (st == 6) cp_async_wait<1>();
        else              cp_async_wait<0>();
        __syncthreads();   // data visible to all warps (also covers W, st==0)

        const float* buf = Abuf + (st & 3) * STAGE_WORDS;
#pragma unroll
        for (int kk = 0; kk < 2; kk++) {
            const int cb = kk * 8;
            unsigned a0 = f2tf32(buf[(16 * w + g) * A_P + cb + t]);
            unsigned a1 = f2tf32(buf[(16 * w + g + 8) * A_P + cb + t]);
            unsigned a2 = f2tf32(buf[(16 * w + g) * A_P + cb + t + 4]);
            unsigned a3 = f2tf32(buf[(16 * w + g + 8) * A_P + cb + t + 4]);
            const unsigned* wb0 = Ws + (st * STAGE_COLS + cb + t) * WS_PITCH + g;
            const unsigned* wb1 = Ws + (st * STAGE_COLS + cb + t + 4) * WS_PITCH + g;
#pragma unroll
            for (int j = 0; j < 16; j++) {
                unsigned b0 = wb0[8 * j];
                unsigned b1 = wb1[8 * j];
                mma_tf32(acc[j][0], acc[j][1], acc[j][2], acc[j][3],
                         a0, a1, a2, a3, b0, b1);
            }
        }
        __syncthreads();   // all warps done reading the buffer
        if (st + PIPE < N_STAGES) issue_stage(st + PIPE);
    }

    // ---- epilogue: fp16 store + per-head logits (R8, unchanged) ----
    const int rw = row0 + 16 * w;
#pragma unroll
    for (int j = 0; j < 16; j++) {
        float c0 = acc[j][0], c1 = acc[j][1], c2 = acc[j][2], c3 = acc[j][3];
        int colb = 8 * j + 2 * t;
        float2 sv = __ldg(reinterpret_cast<const float2*>(a_src + colb));
        float2 dv = __ldg(reinterpret_cast<const float2*>(a_dst + colb));
        float s0 = c0 * sv.x + c1 * sv.y;
        float d0 = c0 * dv.x + c1 * dv.y;
        float s1 = c2 * sv.x + c3 * sv.y;
        float d1 = c2 * dv.x + c3 * dv.y;
        s0 += __shfl_xor_sync(0xffffffffu, s0, 1);
        s0 += __shfl_xor_sync(0xffffffffu, s0, 2);
        d0 += __shfl_xor_sync(0xffffffffu, d0, 1);
        d0 += __shfl_xor_sync(0xffffffffu, d0, 2);
        s1 += __shfl_xor_sync(0xffffffffu, s1, 1);
        s1 += __shfl_xor_sync(0xffffffffu, s1, 2);
        d1 += __shfl_xor_sync(0xffffffffu, d1, 1);
        d1 += __shfl_xor_sync(0xffffffffu, d1, 2);

        int r0v = rw + g, r1v = rw + g + 8;
        if (r0v < M) {
            __half2 p = __floats2half2_rn(c0, c1);
            *reinterpret_cast<__half2*>(g_xh16 + (size_t)r0v * HIDD + colb) = p;
            if (t == 0) {
                g_als[r0v * HEADS + j] = s0;
                g_ald[r0v * HEADS + j] = d0;
            }
        }
        if (r1v < M) {
            __half2 p = __floats2half2_rn(c2, c3);
            *reinterpret_cast<__half2*>(g_xh16 + (size_t)r1v * HIDD + colb) = p;
            if (t == 0) {
                g_als[r1v * HEADS + j] = s1;
                g_ald[r1v * HEADS + j] = d1;
            }
        }
    }
}

// ---------------- fused aggregation v3: half-warp per NODE (R16 best) ------
__device__ __forceinline__ void load_msg8(const __half* p, float* f) {
    uint4 raw = __ldg(reinterpret_cast<const uint4*>(p));
    const __half2* h = reinterpret_cast<const __half2*>(&raw);
#pragma unroll
    for (int i = 0; i < 4; i++) {
        float2 v = __half22float2(h[i]);
        f[2 * i]     = v.x;
        f[2 * i + 1] = v.y;
    }
}

template <int LAYER>
__global__ void aggregate_kernel(const float* __restrict__ bias,
                                 float* __restrict__ outbuf) {
    const int warp = (blockIdx.x * blockDim.x + threadIdx.x) >> 5;
    const int lane = threadIdx.x & 31;
    const int hl   = lane & 15;               // head owned by this lane
    const int n    = warp * 2 + (lane >> 4);  // node for this half-warp
    if (n >= NN) return;

    const float ald_h = __ldg(g_ald + n * HEADS + hl);

    float acc[8];
    float denom;

    // self loop
    {
        float v = __ldg(g_als + n * HEADS + hl) + ald_h;
        float lr = v > 0.f ? v : 0.2f * v;
        float ex = __expf(lr);
        float f[8];
        load_msg8(g_xh16 + (size_t)n * HIDD + hl * 8, f);
#pragma unroll
        for (int i = 0; i < 8; i++) acc[i] = ex * f[i];
        denom = ex;
    }

    const int beg = __ldg(g_off + n);
    const int deg = __ldg(g_off + n + 1) - beg;

#pragma unroll 4
    for (int k = 0; k < deg; k++) {
        int src = __ldg(g_srclist + beg + k);   // broadcast within half-warp
        float v = __ldg(g_als + src * HEADS + hl) + ald_h;
        float lr = v > 0.f ? v : 0.2f * v;
        float ex = __expf(lr);
        float f[8];
        load_msg8(g_xh16 + (size_t)src * HIDD + hl * 8, f);
#pragma unroll
        for (int i = 0; i < 8; i++) acc[i] = fmaf(ex, f[i], acc[i]);
        denom += ex;
    }

    float inv = 1.f / (denom + 1e-16f);
    float4 b0 = *reinterpret_cast<const float4*>(bias + hl * 8);
    float4 b1 = *reinterpret_cast<const float4*>(bias + hl * 8 + 4);
    float4 r0, r1;
    r0.x = acc[0] * inv + b0.x;
    r0.y = acc[1] * inv + b0.y;
    r0.z = acc[2] * inv + b0.z;
    r0.w = acc[3] * inv + b0.w;
    r1.x = acc[4] * inv + b1.x;
    r1.y = acc[5] * inv + b1.y;
    r1.z = acc[6] * inv + b1.z;
    r1.w = acc[7] * inv + b1.w;
    if (LAYER == 0) {
        r0.x = r0.x > 0.f ? r0.x : expm1f(r0.x);
        r0.y = r0.y > 0.f ? r0.y : expm1f(r0.y);
        r0.z = r0.z > 0.f ? r0.z : expm1f(r0.z);
        r0.w = r0.w > 0.f ? r0.w : expm1f(r0.w);
        r1.x = r1.x > 0.f ? r1.x : expm1f(r1.x);
        r1.y = r1.y > 0.f ? r1.y : expm1f(r1.y);
        r1.z = r1.z > 0.f ? r1.z : expm1f(r1.z);
        r1.w = r1.w > 0.f ? r1.w : expm1f(r1.w);
        *reinterpret_cast<float4*>(g_h + (size_t)n * HIDD + hl * 8)     = r0;
        *reinterpret_cast<float4*>(g_h + (size_t)n * HIDD + hl * 8 + 4) = r1;
    } else {
        *reinterpret_cast<float4*>(outbuf + (size_t)n * HIDD + hl * 8)     = r0;
        *reinterpret_cast<float4*>(outbuf + (size_t)n * HIDD + hl * 8 + 4) = r1;
    }
}

// ---------------- launch ------------------------------------------------------
extern "C" void kernel_launch(void* const* d_in, const int* in_sizes, int n_in,
                              void* d_out, int out_size) {
    const float* x   = (const float*)d_in[0];
    const int*   ei  = (const int*)d_in[1];
    const float* W1  = (const float*)d_in[2];
    const float* as1 = (const float*)d_in[3];
    const float* ad1 = (const float*)d_in[4];
    const float* b1  = (const float*)d_in[5];
    const float* W2  = (const float*)d_in[6];
    const float* as2 = (const float*)d_in[7];
    const float* ad2 = (const float*)d_in[8];
    const float* b2  = (const float*)d_in[9];
    float* out = (float*)d_out;

    cudaFuncSetAttribute(gemm_kernel<0>, cudaFuncAttributeMaxDynamicSharedMemorySize,
                         GEMM_SMEM_BYTES);
    cudaFuncSetAttribute(gemm_kernel<1>, cudaFuncAttributeMaxDynamicSharedMemorySize,
                         GEMM_SMEM_BYTES);

    const int TB = 256;
    const int gGemm = (NN + GEMM_ROWS - 1) / GEMM_ROWS;
    const int gEdge = (E0C + TB - 1) / TB;
    const int gAgg  = (NN / 2 * 32 + TB - 1) / TB;   // 2 nodes per warp

    // ---- CSR build (g_deg zero-invariant maintained by csr_scan) ----
    csr_hist_kernel<<<gEdge, TB>>>(ei);
    csr_scan_kernel<<<1, 1024>>>();
    csr_scatter_kernel<<<gEdge, TB>>>(ei);

    // ---- layer 1 ----
    gemm_kernel<0><<<gGemm, TB, GEMM_SMEM_BYTES>>>(x, W1, as1, ad1, NN);
    aggregate_kernel<0><<<gAgg, TB>>>(b1, nullptr);

    // ---- layer 2 ----
    gemm_kernel<1><<<gGemm, TB, GEMM_SMEM_BYTES>>>(nullptr, W2, as2, ad2, NN);
    aggregate_kernel<1><<<gAgg, TB>>>(b2, out);
}